// round 10
// baseline (speedup 1.0000x reference)
#include <cuda_runtime.h>

#define CIN    64
#define COUT   64
#define NPTS   2048
#define NBATCH 16
#define BNT    (NBATCH*NPTS)   /* 32768 */
#define KN     20
#define KSN    20
#define PT     8               /* points per block in k_main */
#define NREP   8               /* replicated BN-stat bins */

// ---------------- scratch (static device memory; no allocations) ----------------
__device__ float  g_Y[(size_t)BNT * COUT];        // 8 MB: Y[n][o] = sum_c wb[o,c] x_n[c]
__device__ float  g_Z[(size_t)BNT * COUT];        // 8 MB: Z[n][o] = sum_c (wa-wb)[o,c] x_n[c]
__device__ float  g_outpre[(size_t)BNT * COUT];   // 8 MB: pre-BN output, (b,o,n) layout
__device__ float  g_Wb[COUT * CIN];               // folded wb   [o][c]
__device__ float  g_Wc[COUT * CIN];               // folded wa-wb[o][c]
__device__ float  g_sumf[NREP][COUT];
__device__ float  g_sumsqf[NREP][COUT];

// ------- kernel 0: zero BN bins + fold channel-permute into weights (once) ------
__global__ void k_init(const float* __restrict__ conv_w) {
    int t = threadIdx.x;                 // 256
#pragma unroll
    for (int i = t; i < 2*NREP*COUT; i += 256) {
        if (i < NREP*COUT) ((float*)g_sumf)[i] = 0.f;
        else               ((float*)g_sumsqf)[i - NREP*COUT] = 0.f;
    }
    for (int i = t; i < COUT*CIN; i += 256) {
        int o = i >> 6, c = i & 63;
        // post-permute index p(c) = (c%32)*4 + c/32 ; diff block at old-ch c+64
        float wa = conv_w[o*128 + (c & 31)*4 + (c >> 5)];
        float wb = conv_w[o*128 + (c & 31)*4 + 2 + (c >> 5)];
        g_Wb[i] = wb;
        g_Wc[i] = wa - wb;
    }
}

// ------- kernel A: per-point GEMM  feature -> Y,Z -------------------------------
__global__ void __launch_bounds__(256)
k_feat(const float* __restrict__ feat)
{
    __shared__ float tile[CIN * 32];   // [c][j] 32 points
    __shared__ float Wb[COUT * CIN];   // [o][c]
    __shared__ float Wc[COUT * CIN];   // [o][c]

    const int t  = threadIdx.x;          // 256
    const int ng = blockIdx.x * 32;      // global point base (32 pts, same batch)
    const int b  = ng >> 11, nn = ng & (NPTS - 1);

    for (int i = t; i < COUT*CIN; i += 256) { Wb[i] = g_Wb[i]; Wc[i] = g_Wc[i]; }
    for (int i = t; i < CIN*32; i += 256) {
        int c = i >> 5, j = i & 31;
        tile[c*32 + j] = feat[((size_t)(b*CIN + c))*NPTS + nn + j];
    }
    __syncthreads();

    const int j  = t & 31;            // point within tile
    const int o0 = (t >> 5) * 8;      // o-octet (warp-uniform -> broadcast W reads)

    float x[CIN];
#pragma unroll
    for (int c = 0; c < CIN; c++) x[c] = tile[c*32 + j];

    float* yrow = g_Y + (size_t)(ng + j)*COUT + o0;
    float* zrow = g_Z + (size_t)(ng + j)*COUT + o0;

#pragma unroll
    for (int half = 0; half < 2; half++) {
        const float* W = half ? Wc : Wb;
        float acc[8];
#pragma unroll
        for (int oo = 0; oo < 8; oo++) {
            const float* wr = W + (o0 + oo)*CIN;
            float a = 0.f;
#pragma unroll
            for (int c = 0; c < CIN; c += 4) {
                float4 w4 = *(const float4*)(wr + c);
                a = fmaf(w4.x, x[c],   a);
                a = fmaf(w4.y, x[c+1], a);
                a = fmaf(w4.z, x[c+2], a);
                a = fmaf(w4.w, x[c+3], a);
            }
            acc[oo] = a;
        }
        float* dst = half ? zrow : yrow;
        *(float4*)(dst)     = make_float4(acc[0], acc[1], acc[2], acc[3]);
        *(float4*)(dst + 4) = make_float4(acc[4], acc[5], acc[6], acc[7]);
    }
}

// ------- kernel B: gather Y/Z + P-mix + max + BN partials -----------------------
// 256 thr, PT=8 pts/block, 32 thr/pt (one warp = one point), 2 o-channels/thread.
__global__ void __launch_bounds__(256, 2)
k_main(const int* __restrict__ nidx,          // int32 (JAX x64 disabled)
       const float* __restrict__ perm,
       const float* __restrict__ conv_b)
{
    __shared__ float Ps[PT * KN * KSN];   // [pt][s][k] transposed permatrix (12.8 KB)
    __shared__ float Os[COUT * 9];        // [o][pt] padded

    const int t  = threadIdx.x;
    const int n0 = blockIdx.x * PT;

    // stage P transposed to [s][k] for contiguous float4 reads
    for (int i = t; i < PT*KN*KSN; i += 256) {
        int pt = i / 400, r = i % 400;
        int k = r / 20, s = r % 20;
        Ps[pt*400 + s*20 + k] = perm[(size_t)(n0 + pt)*400 + r];
    }

    const int og = t & 31;    // o-pair: o = og*2, og*2+1
    const int pt = t >> 5;    // point (== warp id)

    const int* nrow = nidx + (n0 + pt)*KN;

    // gather (pure global, overlaps the staging loop above; sync comes after)
    int idx0 = nrow[0] & (BNT - 1);
    float2 Zc = *(const float2*)(g_Z + (size_t)idx0*COUT + og*2);

    float2 Yc[KN];
#pragma unroll
    for (int k = 0; k < KN; k++) {
        int idx = nrow[k] & (BNT - 1);    // identity for valid input
        Yc[k] = *(const float2*)(g_Y + (size_t)idx*COUT + og*2);
    }
#pragma unroll
    for (int k = 0; k < KN; k++) { Yc[k].x += Zc.x; Yc[k].y += Zc.y; }

    __syncthreads();

    float m0 = -3.4e38f, m1 = -3.4e38f;
    const float* prow = Ps + pt*400;
#pragma unroll 2
    for (int s = 0; s < KSN; s++) {
        float p[KN];
#pragma unroll
        for (int q = 0; q < 5; q++) {                 // warp-broadcast LDS.128
            float4 v = *(const float4*)(prow + s*20 + q*4);
            p[q*4+0] = v.x; p[q*4+1] = v.y; p[q*4+2] = v.z; p[q*4+3] = v.w;
        }
        float v0 = 0.f, v1 = 0.f;
#pragma unroll
        for (int k = 0; k < KN; k++) {
            v0 = fmaf(p[k], Yc[k].x, v0);
            v1 = fmaf(p[k], Yc[k].y, v1);
        }
        m0 = fmaxf(m0, v0); m1 = fmaxf(m1, v1);
    }
    m0 += __ldg(conv_b + og*2 + 0);
    m1 += __ldg(conv_b + og*2 + 1);

    Os[(og*2 + 0)*9 + pt] = m0;
    Os[(og*2 + 1)*9 + pt] = m1;
    __syncthreads();

    // BN partials: float atomics into replicated bins
    if (t < COUT) {
        float s1 = 0.f, s2 = 0.f;
#pragma unroll
        for (int q = 0; q < PT; q++) { float v = Os[t*9 + q]; s1 += v; s2 += v*v; }
        int rep = blockIdx.x & (NREP - 1);
        atomicAdd(&g_sumf[rep][t],   s1);
        atomicAdd(&g_sumsqf[rep][t], s2);
    }
    // write pre-BN output in (b, o, n) layout: 64 o x 2 float4 = 128 writes
    if (t < 128) {
        int o  = t >> 1;
        int i0 = (t & 1) * 4;
        int b  = n0 / NPTS, nn = n0 % NPTS;
        float4 v = make_float4(Os[o*9 + i0], Os[o*9 + i0 + 1],
                               Os[o*9 + i0 + 2], Os[o*9 + i0 + 3]);
        *(float4*)(g_outpre + ((size_t)(b*COUT + o))*NPTS + nn + i0) = v;
    }
}

// ---------------- kernel C: finalize BN stats + apply (MLP=4) -------------------
__global__ void k_norm(const float* __restrict__ bn_w, const float* __restrict__ bn_b,
                       float* __restrict__ out) {
    __shared__ float s_scale[COUT], s_shift[COUT];
    int t = threadIdx.x;
    if (t < COUT) {
        float s1 = 0.f, s2 = 0.f;
#pragma unroll
        for (int r = 0; r < NREP; r++) { s1 += g_sumf[r][t]; s2 += g_sumsqf[r][t]; }
        double mean = (double)s1 * (1.0 / (double)BNT);
        double var  = (double)s2 * (1.0 / (double)BNT) - mean*mean;
        float istd  = rsqrtf((float)var + 1e-5f);
        float w     = bn_w[t];
        s_scale[t] = w * istd;
        s_shift[t] = bn_b[t] - (float)mean * istd * w;
    }
    __syncthreads();
    int base = blockIdx.x * 1024 + t;            // 512 blocks x 4 float4/thread
    float4 vv[4]; int oo[4];
#pragma unroll
    for (int q = 0; q < 4; q++) {
        int i4 = base + q*256;
        oo[q] = (i4 >> 9) & 63;
        vv[q] = *(const float4*)(g_outpre + (size_t)i4 * 4);
    }
#pragma unroll
    for (int q = 0; q < 4; q++) {
        int i4 = base + q*256;
        float sc = s_scale[oo[q]], sh = s_shift[oo[q]];
        float4 v = vv[q];
        v.x = v.x*sc + sh; v.y = v.y*sc + sh; v.z = v.z*sc + sh; v.w = v.w*sc + sh;
        ((float4*)out)[i4] = v;
    }
}

// ---------------- launch --------------------------------------------------------
extern "C" void kernel_launch(void* const* d_in, const int* in_sizes, int n_in,
                              void* d_out, int out_size)
{
    const float* feature = (const float*)d_in[0];
    const int*   nidx    = (const int*)d_in[1];     // int32 (JAX x64 disabled)
    const float* perm    = (const float*)d_in[2];
    const float* conv_w  = (const float*)d_in[3];
    const float* conv_b  = (const float*)d_in[4];
    const float* bn_w    = (const float*)d_in[5];
    const float* bn_b    = (const float*)d_in[6];
    float*       out     = (float*)d_out;

    k_init<<<1, 256>>>(conv_w);
    k_feat<<<BNT/32, 256>>>(feature);
    k_main<<<BNT/PT, 256>>>(nidx, perm, conv_b);
    k_norm<<<(BNT*COUT)/(1024*4), 256>>>(bn_w, bn_b, out);
}

// round 12
// speedup vs baseline: 1.3583x; 1.3583x over previous
#include <cuda_runtime.h>

#define CIN    64
#define COUT   64
#define NPTS   2048
#define NBATCH 16
#define BNT    (NBATCH*NPTS)   /* 32768 */
#define KN     20
#define KSN    20
#define PT     8               /* points per block in k_main (128 thr) */
#define NREP   8               /* replicated BN-stat bins */

// ---------------- scratch (static device memory; no allocations) ----------------
__device__ float  g_Y[(size_t)BNT * COUT];        // 8 MB: Y[n][o] = sum_c wb[o,c] x_n[c]
__device__ float  g_Z[(size_t)BNT * COUT];        // 8 MB: Z[n][o] = sum_c (wa-wb)[o,c] x_n[c]
__device__ float  g_outpre[(size_t)BNT * COUT];   // 8 MB: pre-BN output, (b,o,n) layout
__device__ float  g_Wb[COUT * CIN];               // folded wb   [o][c]
__device__ float  g_Wc[COUT * CIN];               // folded wa-wb[o][c]
__device__ float  g_sumf[NREP][COUT];
__device__ float  g_sumsqf[NREP][COUT];

// ------- launch 1: fold channel-permute into weights ----------------------------
__global__ void k_fold(const float* __restrict__ conv_w) {
    int i = threadIdx.x * 16 + 0;        // 256 threads x 16 = 4096
    for (int q = 0; q < 16; q++, i++) {
        int o = i >> 6, c = i & 63;
        // post-permute index p(c) = (c%32)*4 + c/32 ; diff block at old-ch c+64
        float wa = conv_w[o*128 + (c & 31)*4 + (c >> 5)];
        float wb = conv_w[o*128 + (c & 31)*4 + 2 + (c >> 5)];
        g_Wb[i] = wb;
        g_Wc[i] = wa - wb;
    }
}

// ------- launch 3: zero replicated BN-stat bins ---------------------------------
__global__ void k_zero() {
    int t = threadIdx.x;                 // 1024
    if (t < NREP*COUT)  ((float*)g_sumf)[t] = 0.f;
    else if (t < 2*NREP*COUT) ((float*)g_sumsqf)[t - NREP*COUT] = 0.f;
}

// ------- launch 2: per-point GEMM  feature -> Y,Z -------------------------------
__global__ void __launch_bounds__(256)
k_feat(const float* __restrict__ feat)
{
    __shared__ float tile[CIN * 32];   // [c][j] 32 points
    __shared__ float Wb[COUT * CIN];   // [o][c]
    __shared__ float Wc[COUT * CIN];   // [o][c]

    const int t  = threadIdx.x;          // 256
    const int ng = blockIdx.x * 32;      // global point base (32 pts, same batch)
    const int b  = ng >> 11, nn = ng & (NPTS - 1);

    for (int i = t; i < COUT*CIN; i += 256) { Wb[i] = g_Wb[i]; Wc[i] = g_Wc[i]; }
    for (int i = t; i < CIN*32; i += 256) {
        int c = i >> 5, j = i & 31;
        tile[c*32 + j] = feat[((size_t)(b*CIN + c))*NPTS + nn + j];
    }
    __syncthreads();

    const int j  = t & 31;            // point within tile
    const int o0 = (t >> 5) * 8;      // o-octet (warp-uniform -> broadcast W reads)

    float x[CIN];
#pragma unroll
    for (int c = 0; c < CIN; c++) x[c] = tile[c*32 + j];

    float* yrow = g_Y + (size_t)(ng + j)*COUT + o0;
    float* zrow = g_Z + (size_t)(ng + j)*COUT + o0;

#pragma unroll
    for (int half = 0; half < 2; half++) {
        const float* W = half ? Wc : Wb;
        float acc[8];
#pragma unroll
        for (int oo = 0; oo < 8; oo++) {
            const float* wr = W + (o0 + oo)*CIN;
            float a = 0.f;
#pragma unroll
            for (int c = 0; c < CIN; c += 4) {
                float4 w4 = *(const float4*)(wr + c);
                a = fmaf(w4.x, x[c],   a);
                a = fmaf(w4.y, x[c+1], a);
                a = fmaf(w4.z, x[c+2], a);
                a = fmaf(w4.w, x[c+3], a);
            }
            acc[oo] = a;
        }
        float* dst = half ? zrow : yrow;
        *(float4*)(dst)     = make_float4(acc[0], acc[1], acc[2], acc[3]);
        *(float4*)(dst + 4) = make_float4(acc[4], acc[5], acc[6], acc[7]);
    }
}

// ------- launch 4: gather Y/Z + P-mix + max + BN partials -----------------------
// 128 thr, PT=8: 16 thr/point, 4 o-channels/thread (the proven R9 shape),
// no occupancy pin -> ~160 regs, 3 CTAs/SM by register limit.
__global__ void __launch_bounds__(128)
k_main(const int* __restrict__ nidx,          // int32 (JAX x64 disabled)
       const float* __restrict__ perm,
       const float* __restrict__ conv_b)
{
    __shared__ float Ps[PT * KN * KSN];   // [pt][s][k] transposed permatrix (12.8 KB)
    __shared__ float Os[COUT * 9];        // [o][pt] padded (2.3 KB)

    const int t  = threadIdx.x;
    const int n0 = blockIdx.x * PT;

    // stage P transposed to [s][k] for contiguous float4 reads
    for (int i = t; i < PT*KN*KSN; i += 128) {
        int pt = i / 400, r = i % 400;
        int k = r / 20, s = r % 20;
        Ps[pt*400 + s*20 + k] = perm[(size_t)(n0 + pt)*400 + r];
    }

    const int og = t & 15;    // o-quad: o = og*4 .. og*4+3
    const int pt = t >> 4;    // point within block (0..7)

    const int* nrow = nidx + (n0 + pt)*KN;

    // gather: 16 lanes x float4 = one full 256B Y row per half-warp, coalesced.
    // Issued before the sync so LDGs overlap the Ps staging latency.
    int idx0 = nrow[0] & (BNT - 1);
    float4 Zc = *(const float4*)(g_Z + (size_t)idx0*COUT + og*4);

    float4 Yc[KN];
#pragma unroll
    for (int k = 0; k < KN; k++) {
        int idx = nrow[k] & (BNT - 1);    // identity for valid input
        Yc[k] = *(const float4*)(g_Y + (size_t)idx*COUT + og*4);
    }
#pragma unroll
    for (int k = 0; k < KN; k++) {
        Yc[k].x += Zc.x; Yc[k].y += Zc.y; Yc[k].z += Zc.z; Yc[k].w += Zc.w;
    }

    __syncthreads();

    float m0 = -3.4e38f, m1 = -3.4e38f, m2 = -3.4e38f, m3 = -3.4e38f;
    const float* prow = Ps + pt*400;
#pragma unroll 2
    for (int s = 0; s < KSN; s++) {
        float p[KN];
#pragma unroll
        for (int q = 0; q < 5; q++) {
            float4 v = *(const float4*)(prow + s*20 + q*4);
            p[q*4+0] = v.x; p[q*4+1] = v.y; p[q*4+2] = v.z; p[q*4+3] = v.w;
        }
        float v0 = 0.f, v1 = 0.f, v2 = 0.f, v3 = 0.f;
#pragma unroll
        for (int k = 0; k < KN; k++) {
            v0 = fmaf(p[k], Yc[k].x, v0);
            v1 = fmaf(p[k], Yc[k].y, v1);
            v2 = fmaf(p[k], Yc[k].z, v2);
            v3 = fmaf(p[k], Yc[k].w, v3);
        }
        m0 = fmaxf(m0, v0); m1 = fmaxf(m1, v1);
        m2 = fmaxf(m2, v2); m3 = fmaxf(m3, v3);
    }
    m0 += __ldg(conv_b + og*4 + 0);
    m1 += __ldg(conv_b + og*4 + 1);
    m2 += __ldg(conv_b + og*4 + 2);
    m3 += __ldg(conv_b + og*4 + 3);

    Os[(og*4 + 0)*9 + pt] = m0;
    Os[(og*4 + 1)*9 + pt] = m1;
    Os[(og*4 + 2)*9 + pt] = m2;
    Os[(og*4 + 3)*9 + pt] = m3;
    __syncthreads();

    // BN partials: float atomics into replicated bins
    if (t < COUT) {
        float s1 = 0.f, s2 = 0.f;
#pragma unroll
        for (int q = 0; q < PT; q++) { float v = Os[t*9 + q]; s1 += v; s2 += v*v; }
        int rep = blockIdx.x & (NREP - 1);
        atomicAdd(&g_sumf[rep][t],   s1);
        atomicAdd(&g_sumsqf[rep][t], s2);
    }
    // write pre-BN output in (b, o, n) layout: 64 o x 2 float4 = 128 writes
    {
        int o  = t >> 1;
        int i0 = (t & 1) * 4;
        int b  = n0 / NPTS, nn = n0 % NPTS;
        float4 v = make_float4(Os[o*9 + i0], Os[o*9 + i0 + 1],
                               Os[o*9 + i0 + 2], Os[o*9 + i0 + 3]);
        *(float4*)(g_outpre + ((size_t)(b*COUT + o))*NPTS + nn + i0) = v;
    }
}

// ------- launch 5: finalize BN stats + apply (MLP=4) ----------------------------
__global__ void k_norm(const float* __restrict__ bn_w, const float* __restrict__ bn_b,
                       float* __restrict__ out) {
    __shared__ float s_scale[COUT], s_shift[COUT];
    int t = threadIdx.x;
    if (t < COUT) {
        float s1 = 0.f, s2 = 0.f;
#pragma unroll
        for (int r = 0; r < NREP; r++) { s1 += g_sumf[r][t]; s2 += g_sumsqf[r][t]; }
        double mean = (double)s1 * (1.0 / (double)BNT);
        double var  = (double)s2 * (1.0 / (double)BNT) - mean*mean;
        float istd  = rsqrtf((float)var + 1e-5f);
        float w     = bn_w[t];
        s_scale[t] = w * istd;
        s_shift[t] = bn_b[t] - (float)mean * istd * w;
    }
    __syncthreads();
    int base = blockIdx.x * 1024 + t;            // 512 blocks x 4 float4/thread
    float4 vv[4]; int oo[4];
#pragma unroll
    for (int q = 0; q < 4; q++) {
        int i4 = base + q*256;
        oo[q] = (i4 >> 9) & 63;
        vv[q] = *(const float4*)(g_outpre + (size_t)i4 * 4);
    }
#pragma unroll
    for (int q = 0; q < 4; q++) {
        int i4 = base + q*256;
        float sc = s_scale[oo[q]], sh = s_shift[oo[q]];
        float4 v = vv[q];
        v.x = v.x*sc + sh; v.y = v.y*sc + sh; v.z = v.z*sc + sh; v.w = v.w*sc + sh;
        ((float4*)out)[i4] = v;
    }
}

// ---------------- launch --------------------------------------------------------
extern "C" void kernel_launch(void* const* d_in, const int* in_sizes, int n_in,
                              void* d_out, int out_size)
{
    const float* feature = (const float*)d_in[0];
    const int*   nidx    = (const int*)d_in[1];     // int32 (JAX x64 disabled)
    const float* perm    = (const float*)d_in[2];
    const float* conv_w  = (const float*)d_in[3];
    const float* conv_b  = (const float*)d_in[4];
    const float* bn_w    = (const float*)d_in[5];
    const float* bn_b    = (const float*)d_in[6];
    float*       out     = (float*)d_out;

    k_fold<<<1, 256>>>(conv_w);                            // launch 1
    k_feat<<<BNT/32, 256>>>(feature);                      // launch 2
    k_zero<<<1, 1024>>>();                                 // launch 3
    k_main<<<BNT/PT, 128>>>(nidx, perm, conv_b);           // launch 4 <- ncu slot
    k_norm<<<(BNT*COUT)/(1024*4), 256>>>(bn_w, bn_b, out); // launch 5
}